// round 15
// baseline (speedup 1.0000x reference)
#include <cuda_runtime.h>
#include <cstdint>

// ---- problem constants ----
#define T_DIM   128
#define C_DIM   64
#define F_DIM   64
#define K_DIM   128          // filters (full); per-CTA M = 64
#define CP      62
#define N_TOTAL 4096
#define BN_EPS  1e-3f

#define NROWS   4            // fused rows per CTA -> GEMM N = 256
#define THREADS 256
#define M_CTA   64
#define NSTG    12           // stages of 2 kc (K = 192 = 24 kc)
#define RING    2
#define BROW_W  12           // B row stride words (48 B) -> conflict-free lds32

// smem: Afrag[24 kc][4 mt][32 lane][4] floats = 12288, then Bs[2][2 kc][256 n][12]
#define A_FLOATS 12288
#define STG_FLOATS (2 * 256 * BROW_W)    // 6144 floats
#define B_FLOATS (RING * STG_FLOATS)     // 12288
#define SMEM_BYTES ((A_FLOATS + B_FLOATS) * 4)   // 98304 per CTA (x2 = 192 KB/SM)
#define STG_BYTES  (STG_FLOATS * 4)      // 24576
#define KC_BYTES   (256 * BROW_W * 4)    // 12288

// epilogue smem reuse: per-warp [32 cp][pitch 68] floats
#define EPI_PITCH 68
#define EPI_WARP  (32 * EPI_PITCH)       // 2176 x 8 warps = 17408 <= 24576

__device__ __forceinline__ uint32_t smem_u32(const void* p) {
    uint32_t a;
    asm("{ .reg .u64 t; cvta.to.shared.u64 t, %1; cvt.u32.u64 %0, t; }" : "=r"(a) : "l"(p));
    return a;
}
__device__ __forceinline__ float tf32r(float v) {
    uint32_t u;
    asm("cvt.rna.tf32.f32 %0, %1;" : "=r"(u) : "f"(v));
    return __uint_as_float(u);
}
__device__ __forceinline__ void cp_async16(uint32_t dst, const void* src, int sz) {
    asm volatile("cp.async.ca.shared.global [%0], [%1], 16, %2;"
                 :: "r"(dst), "l"(src), "r"(sz) : "memory");
}
#define CP_COMMIT() asm volatile("cp.async.commit_group;" ::: "memory")
#define CP_WAIT1()  asm volatile("cp.async.wait_group 1;" ::: "memory")

__device__ __forceinline__ void lds128(uint32_t a, uint32_t* v) {
    asm volatile("ld.shared.v4.b32 {%0,%1,%2,%3}, [%4];"
                 : "=r"(v[0]), "=r"(v[1]), "=r"(v[2]), "=r"(v[3]) : "r"(a));
}
__device__ __forceinline__ uint32_t lds32(uint32_t a) {
    uint32_t v;
    asm volatile("ld.shared.b32 %0, [%1];" : "=r"(v) : "r"(a));
    return v;
}

__global__ __launch_bounds__(THREADS, 2)
void tccnn_mma7_kernel(const float* __restrict__ x,
                       const float* __restrict__ conv_w,
                       const float* __restrict__ conv_b,
                       const float* __restrict__ bn_gamma,
                       const float* __restrict__ bn_beta,
                       const float* __restrict__ bn_mean,
                       const float* __restrict__ bn_var,
                       float* __restrict__ out)
{
    extern __shared__ float smem[];
    const uint32_t as_addr = smem_u32(smem);
    const uint32_t bs_addr = as_addr + A_FLOATS * 4;

    const int tid  = threadIdx.x;
    const int lane = tid & 31;
    const int wid  = tid >> 5;           // 0..7
    const int r    = lane >> 2;          // 0..7
    const int cql  = lane & 3;           // 0..3
    const int row  = wid >> 1;           // fused row 0..3
    const int nhalf= (wid & 1) * 32;     // cp origin within row
    const int m0c  = (blockIdx.x & 1) * M_CTA;       // filter half
    const int n0c  = (blockIdx.x >> 1) * NROWS;

    // ---- stage A as ready fragments for this CTA's M half:
    // frag f = kc*128 + mt8*32 + lane; holds {w[kl][gm], w[kl][gm+8], w[kh][gm], w[kh][gm+8]}
    // kl = 8*kc + (ln&3), kh = kl+4, gm = m0c + 16*mt8 + (ln>>2)
    #pragma unroll
    for (int i = 0; i < 12; ++i) {
        const int f   = tid + 256 * i;
        const int kc  = f >> 7;
        const int mt8 = (f >> 5) & 3;
        const int ln  = f & 31;
        const int kl  = 8 * kc + (ln & 3);
        const int kh2 = kl + 4;
        const int gm  = m0c + 16 * mt8 + (ln >> 2);
        float4 v;
        v.x = tf32r(conv_w[kl  * K_DIM + gm]);
        v.y = tf32r(conv_w[kl  * K_DIM + gm + 8]);
        v.z = tf32r(conv_w[kh2 * K_DIM + gm]);
        v.w = tf32r(conv_w[kh2 * K_DIM + gm + 8]);
        ((float4*)smem)[f] = v;
    }

    // ---- cp.async source/dst bases: thread nb = tid covers n row nb, both k-halves ----
    const int cpt = tid & 63;
    const float* xrow = x + (size_t)(n0c + (tid >> 6)) * (C_DIM * F_DIM);
    const float* psrc[3];
    int szs[3];
    #pragma unroll
    for (int kh = 0; kh < 3; ++kh) {
        const int c  = cpt + kh;
        psrc[kh] = xrow + ((c < C_DIM) ? c : 0) * F_DIM;
        szs[kh]  = (c < C_DIM) ? 16 : 0;
    }
    const uint32_t dstb = bs_addr + (uint32_t)(48 * tid);

    // fill stage si (2 kc) into ring slot
    auto fill_stage = [&](int si, int slot) {
        #pragma unroll
        for (int j = 0; j < 2; ++j) {
            const int sk = 2 * si + j;
            const float* s = psrc[sk >> 3] + ((sk & 7) << 3);
            const int   sz = szs[sk >> 3];
            const uint32_t d = dstb + slot * STG_BYTES + j * KC_BYTES;
            cp_async16(d,      s,     sz);
            cp_async16(d + 16, s + 4, sz);
        }
    };

    fill_stage(0, 0); CP_COMMIT();

    float acc[4][4][4];
    #pragma unroll
    for (int mt = 0; mt < 4; ++mt)
        #pragma unroll
        for (int nt = 0; nt < 4; ++nt)
            #pragma unroll
            for (int q = 0; q < 4; ++q)
                acc[mt][nt][q] = 0.0f;

    // per-warp invariant smem bases
    const uint32_t aw = as_addr + (uint32_t)(lane * 16);
    const uint32_t bw = bs_addr + (uint32_t)(((row * 64 + nhalf + r) * BROW_W + cql) * 4);

    // ---- mainloop: 12 stages x 2 kc ----
    #pragma unroll 1
    for (int si = 0; si < NSTG; ++si) {
        __syncthreads();            // all warps done reading slot being refilled
        if (si + 1 < NSTG)
            fill_stage(si + 1, (si + 1) & 1);
        CP_COMMIT();
        CP_WAIT1();                 // stage si resident (si+1 still in flight)

        const uint32_t bst = bw + (uint32_t)((si & 1) * STG_BYTES);

        // prefetch B frags for kc j=0
        float bb[2][8];
        #pragma unroll
        for (int nt = 0; nt < 4; ++nt) {
            bb[0][2 * nt]     = __uint_as_float(lds32(bst + nt * (8 * BROW_W * 4)));
            bb[0][2 * nt + 1] = __uint_as_float(lds32(bst + nt * (8 * BROW_W * 4) + 16));
        }

        #pragma unroll
        for (int j = 0; j < 2; ++j) {
            if (j < 1) {
                #pragma unroll
                for (int nt = 0; nt < 4; ++nt) {
                    bb[1][2 * nt]     = __uint_as_float(lds32(bst + KC_BYTES + nt * (8 * BROW_W * 4)));
                    bb[1][2 * nt + 1] = __uint_as_float(lds32(bst + KC_BYTES + nt * (8 * BROW_W * 4) + 16));
                }
            }

            const uint32_t ak = aw + (uint32_t)((2 * si + j) * 2048);
            uint32_t a[4][4];
            lds128(ak,        a[0]);
            lds128(ak + 512,  a[1]);
            lds128(ak + 1024, a[2]);
            lds128(ak + 1536, a[3]);

            const float* bj = bb[j];
            #pragma unroll
            for (int nt = 0; nt < 4; ++nt) {
                const uint32_t b0 = __float_as_uint(bj[2 * nt]);
                const uint32_t b1 = __float_as_uint(bj[2 * nt + 1]);
                #pragma unroll
                for (int mt = 0; mt < 4; ++mt) {
                    asm volatile(
                        "mma.sync.aligned.m16n8k8.row.col.f32.tf32.tf32.f32 "
                        "{%0,%1,%2,%3}, {%4,%5,%6,%7}, {%8,%9}, {%0,%1,%2,%3};"
                        : "+f"(acc[mt][nt][0]), "+f"(acc[mt][nt][1]),
                          "+f"(acc[mt][nt][2]), "+f"(acc[mt][nt][3])
                        : "r"(a[mt][0]), "r"(a[mt][1]), "r"(a[mt][2]), "r"(a[mt][3]),
                          "r"(b0), "r"(b1));
                }
            }
        }
    }

    __syncthreads();   // mainloop smem reads done; reuse smem for epilogue

    // ---- epilogue: bias + BN(t) + ReLU -> smem stage -> coalesced STG ----
    {
        const int n = n0c + row;
        const int t = n & (T_DIM - 1);
        const float inv = rsqrtf(bn_var[t] + BN_EPS);
        const float s   = bn_gamma[t] * inv;
        const float sh  = bn_beta[t] - bn_mean[t] * s;

        float* buf = smem + wid * EPI_WARP;   // [32 cp][68]

        #pragma unroll
        for (int mt = 0; mt < 4; ++mt) {
            const int ml = 16 * mt + r;       // local m (0..63)
            const int mh = ml + 8;
            const float bl = conv_b[m0c + ml];
            const float bh = conv_b[m0c + mh];
            #pragma unroll
            for (int nt = 0; nt < 4; ++nt) {
                const int cp0 = 8 * nt + 2 * cql;
                buf[cp0       * EPI_PITCH + ml] = fmaxf((acc[mt][nt][0] + bl) * s + sh, 0.f);
                buf[(cp0 + 1) * EPI_PITCH + ml] = fmaxf((acc[mt][nt][1] + bl) * s + sh, 0.f);
                buf[cp0       * EPI_PITCH + mh] = fmaxf((acc[mt][nt][2] + bh) * s + sh, 0.f);
                buf[(cp0 + 1) * EPI_PITCH + mh] = fmaxf((acc[mt][nt][3] + bh) * s + sh, 0.f);
            }
        }
        __syncwarp();

        float* outn = out + (size_t)n * (CP * K_DIM) + m0c;
        const int cph = lane >> 4;            // 0/1
        const int m4  = 4 * (lane & 15);      // 0..60
        #pragma unroll
        for (int it = 0; it < 16; ++it) {
            const int cp  = 2 * it + cph;     // local 0..31
            const int cpg = nhalf + cp;
            if (cpg < CP) {
                const float4 v = *(const float4*)(buf + cp * EPI_PITCH + m4);
                *(float4*)(outn + cpg * K_DIM + m4) = v;
            }
        }
    }
}

extern "C" void kernel_launch(void* const* d_in, const int* in_sizes, int n_in,
                              void* d_out, int out_size)
{
    const float* x        = (const float*)d_in[0];
    const float* conv_w   = (const float*)d_in[1];
    const float* conv_b   = (const float*)d_in[2];
    const float* bn_gamma = (const float*)d_in[3];
    const float* bn_beta  = (const float*)d_in[4];
    const float* bn_mean  = (const float*)d_in[5];
    const float* bn_var   = (const float*)d_in[6];
    float* out = (float*)d_out;

    cudaFuncSetAttribute(tccnn_mma7_kernel,
                         cudaFuncAttributeMaxDynamicSharedMemorySize, SMEM_BYTES);

    tccnn_mma7_kernel<<<2 * (N_TOTAL / NROWS), THREADS, SMEM_BYTES>>>(
        x, conv_w, conv_b, bn_gamma, bn_beta, bn_mean, bn_var, out);
}

// round 17
// speedup vs baseline: 1.4669x; 1.4669x over previous
#include <cuda_runtime.h>
#include <cstdint>

// ---- problem constants ----
#define T_DIM   128
#define C_DIM   64
#define F_DIM   64
#define K_DIM   128          // filters = GEMM M
#define CP      62
#define N_TOTAL 4096
#define BN_EPS  1e-3f

#define NROWS   4            // fused rows per CTA -> GEMM N = 256
#define THREADS 512
#define NKC     24           // K chunks of 8 (K = 192)

// x tile: per fused row 66 c-rows (64 + 2 halo) x stride 68 words
#define XROW_W  68
#define XROW_FLOATS (66 * XROW_W)        // 4488
#define X_FLOATS (NROWS * XROW_FLOATS)   // 17952

// A frags: [24 kc][8 mt][32 lane][4] floats
#define A_FLOATS 24576
#define SMEM_BYTES ((A_FLOATS + X_FLOATS) * 4)   // 170112

// epilogue smem reuse: per-warp [32 cp][pitch 68]
#define EPI_PITCH 68
#define EPI_WARP  (32 * EPI_PITCH)       // 2176 floats x16 warps = 139264 B, fits

__device__ __forceinline__ uint32_t smem_u32(const void* p) {
    uint32_t a;
    asm("{ .reg .u64 t; cvta.to.shared.u64 t, %1; cvt.u32.u64 %0, t; }" : "=r"(a) : "l"(p));
    return a;
}
__device__ __forceinline__ float tf32r(float v) {
    uint32_t u;
    asm("cvt.rna.tf32.f32 %0, %1;" : "=r"(u) : "f"(v));
    return __uint_as_float(u);
}
__device__ __forceinline__ void cp_async16(uint32_t dst, const void* src) {
    asm volatile("cp.async.ca.shared.global [%0], [%1], 16;"
                 :: "r"(dst), "l"(src) : "memory");
}
#define CP_WAIT_ALL() asm volatile("cp.async.wait_all;" ::: "memory")

__device__ __forceinline__ void lds128(uint32_t a, uint32_t* v) {
    asm volatile("ld.shared.v4.b32 {%0,%1,%2,%3}, [%4];"
                 : "=r"(v[0]), "=r"(v[1]), "=r"(v[2]), "=r"(v[3]) : "r"(a));
}
__device__ __forceinline__ uint32_t lds32(uint32_t a) {
    uint32_t v;
    asm volatile("ld.shared.b32 %0, [%1];" : "=r"(v) : "r"(a));
    return v;
}

__global__ __launch_bounds__(THREADS, 1)
void tccnn_mma8_kernel(const float* __restrict__ x,
                       const float* __restrict__ conv_w,
                       const float* __restrict__ conv_b,
                       const float* __restrict__ bn_gamma,
                       const float* __restrict__ bn_beta,
                       const float* __restrict__ bn_mean,
                       const float* __restrict__ bn_var,
                       float* __restrict__ out)
{
    extern __shared__ float smem[];
    const uint32_t as_addr = smem_u32(smem);
    const uint32_t xs_addr = as_addr + A_FLOATS * 4;
    float* Xs = smem + A_FLOATS;

    const int tid  = threadIdx.x;
    const int lane = tid & 31;
    const int wid  = tid >> 5;           // 0..15
    const int r    = lane >> 2;          // 0..7
    const int cql  = lane & 3;           // 0..3
    const int m0w  = (wid & 1) * 64;     // M origin: 2 m-warps
    const int nw   = wid >> 1;           // 0..7 n-slice
    const int row  = nw >> 1;            // fused row 0..3
    const int nhalf= (nw & 1) * 32;      // cp origin within row
    const int n0c  = blockIdx.x * NROWS;

    // ---- stage A as ready fragments (R14 layout):
    // frag f = kc*256 + mt8*32 + lane = {w[kl][ml], w[kl][ml+8], w[kh][ml], w[kh][ml+8]}
    #pragma unroll
    for (int i = 0; i < 12; ++i) {
        const int f   = tid + 512 * i;
        const int kc  = f >> 8;
        const int mt8 = (f >> 5) & 7;
        const int ln  = f & 31;
        const int kl  = 8 * kc + (ln & 3);
        const int kh2 = kl + 4;
        const int ml  = 16 * mt8 + (ln >> 2);
        float4 v;
        v.x = tf32r(conv_w[kl  * K_DIM + ml]);
        v.y = tf32r(conv_w[kl  * K_DIM + ml + 8]);
        v.z = tf32r(conv_w[kh2 * K_DIM + ml]);
        v.w = tf32r(conv_w[kh2 * K_DIM + ml + 8]);
        ((float4*)smem)[f] = v;
    }

    // ---- zero halo rows (c = 64, 65 per fused row): 4*2*68 = 544 words ----
    if (tid < 544) {
        const int rw = tid / 136;        // fused row
        const int w  = tid % 136;        // 0..135 -> rows 64,65
        Xs[rw * XROW_FLOATS + 64 * XROW_W + w] = 0.0f;
    }

    // ---- fill x tile: 4 rows x 64 c x 64 w = 4096 chunks of 16B, 8 per thread ----
    #pragma unroll
    for (int i = 0; i < 8; ++i) {
        const int id = tid + 512 * i;
        const int q  = id & 15;          // 16B chunk within c-row
        const int c  = (id >> 4) & 63;
        const int rw = id >> 10;
        const uint32_t dst = xs_addr
            + (uint32_t)((rw * XROW_FLOATS + c * XROW_W + 4 * q) * 4);
        cp_async16(dst, x + (size_t)(n0c + rw) * (C_DIM * F_DIM) + c * F_DIM + 4 * q);
    }
    CP_WAIT_ALL();
    __syncthreads();

    float acc[4][4][4];
    #pragma unroll
    for (int mt = 0; mt < 4; ++mt)
        #pragma unroll
        for (int nt = 0; nt < 4; ++nt)
            #pragma unroll
            for (int q = 0; q < 4; ++q)
                acc[mt][nt][q] = 0.0f;

    // per-warp invariant smem bases
    const uint32_t aw = as_addr + (uint32_t)(((wid & 1) * 4 * 32 + lane) * 16);
    // B base: x word (row*4488 + (nhalf + 8nt + r + kh)*68 + kw0 + cql)
    const uint32_t bwb = xs_addr
        + (uint32_t)((row * XROW_FLOATS + (nhalf + r) * XROW_W + cql) * 4);

    // B fragment loader for K-chunk kc
    auto load_b = [&](float* bb, int kc) {
        const uint32_t bk = bwb + (uint32_t)(((kc >> 3) * XROW_W + ((kc & 7) << 3)) * 4);
        #pragma unroll
        for (int nt = 0; nt < 4; ++nt) {
            const uint32_t a0 = bk + (uint32_t)(nt * (8 * XROW_W * 4));
            bb[2 * nt]     = __uint_as_float(lds32(a0));
            bb[2 * nt + 1] = __uint_as_float(lds32(a0 + 16));
        }
    };

    float bb[2][8];
    load_b(bb[0], 0);

    // ---- barrier-free mainloop: 24 kc ----
    #pragma unroll 1
    for (int kc = 0; kc < NKC; ++kc) {
        if (kc + 1 < NKC)
            load_b(bb[(kc + 1) & 1], kc + 1);

        const uint32_t ak = aw + (uint32_t)(kc * 4096);
        uint32_t a[4][4];
        lds128(ak,        a[0]);
        lds128(ak + 512,  a[1]);
        lds128(ak + 1024, a[2]);
        lds128(ak + 1536, a[3]);

        const float* bj = bb[kc & 1];
        #pragma unroll
        for (int nt = 0; nt < 4; ++nt) {
            const uint32_t b0 = __float_as_uint(bj[2 * nt]);
            const uint32_t b1 = __float_as_uint(bj[2 * nt + 1]);
            #pragma unroll
            for (int mt = 0; mt < 4; ++mt) {
                asm volatile(
                    "mma.sync.aligned.m16n8k8.row.col.f32.tf32.tf32.f32 "
                    "{%0,%1,%2,%3}, {%4,%5,%6,%7}, {%8,%9}, {%0,%1,%2,%3};"
                    : "+f"(acc[mt][nt][0]), "+f"(acc[mt][nt][1]),
                      "+f"(acc[mt][nt][2]), "+f"(acc[mt][nt][3])
                    : "r"(a[mt][0]), "r"(a[mt][1]), "r"(a[mt][2]), "r"(a[mt][3]),
                      "r"(b0), "r"(b1));
            }
        }
    }

    __syncthreads();   // mainloop smem reads done; reuse smem for epilogue

    // ---- epilogue: bias + BN(t) + ReLU -> smem stage -> coalesced STG ----
    {
        const int n = n0c + row;
        const int t = n & (T_DIM - 1);
        const float inv = rsqrtf(bn_var[t] + BN_EPS);
        const float s   = bn_gamma[t] * inv;
        const float sh  = bn_beta[t] - bn_mean[t] * s;

        float* buf = smem + wid * EPI_WARP;   // [32 cp][68]

        #pragma unroll
        for (int mt = 0; mt < 4; ++mt) {
            const int ml = 16 * mt + r;
            const int mh = ml + 8;
            const float bl = conv_b[m0w + ml];
            const float bh = conv_b[m0w + mh];
            #pragma unroll
            for (int nt = 0; nt < 4; ++nt) {
                const int cp0 = 8 * nt + 2 * cql;
                buf[cp0       * EPI_PITCH + ml] = fmaxf((acc[mt][nt][0] + bl) * s + sh, 0.f);
                buf[(cp0 + 1) * EPI_PITCH + ml] = fmaxf((acc[mt][nt][1] + bl) * s + sh, 0.f);
                buf[cp0       * EPI_PITCH + mh] = fmaxf((acc[mt][nt][2] + bh) * s + sh, 0.f);
                buf[(cp0 + 1) * EPI_PITCH + mh] = fmaxf((acc[mt][nt][3] + bh) * s + sh, 0.f);
            }
        }
        __syncwarp();

        float* outn = out + (size_t)n * (CP * K_DIM) + m0w;
        const int cph = lane >> 4;            // 0/1
        const int m4  = 4 * (lane & 15);      // 0..60
        #pragma unroll
        for (int it = 0; it < 16; ++it) {
            const int cp  = 2 * it + cph;     // local 0..31
            const int cpg = nhalf + cp;
            if (cpg < CP) {
                const float4 v = *(const float4*)(buf + cp * EPI_PITCH + m4);
                *(float4*)(outn + cpg * K_DIM + m4) = v;
            }
        }
    }
}

extern "C" void kernel_launch(void* const* d_in, const int* in_sizes, int n_in,
                              void* d_out, int out_size)
{
    const float* x        = (const float*)d_in[0];
    const float* conv_w   = (const float*)d_in[1];
    const float* conv_b   = (const float*)d_in[2];
    const float* bn_gamma = (const float*)d_in[3];
    const float* bn_beta  = (const float*)d_in[4];
    const float* bn_mean  = (const float*)d_in[5];
    const float* bn_var   = (const float*)d_in[6];
    float* out = (float*)d_out;

    cudaFuncSetAttribute(tccnn_mma8_kernel,
                         cudaFuncAttributeMaxDynamicSharedMemorySize, SMEM_BYTES);

    tccnn_mma8_kernel<<<N_TOTAL / NROWS, THREADS, SMEM_BYTES>>>(
        x, conv_w, conv_b, bn_gamma, bn_beta, bn_mean, bn_var, out);
}